// round 15
// baseline (speedup 1.0000x reference)
#include <cuda_runtime.h>
#include <cuda_bf16.h>
#include <math.h>
#include <stdint.h>

// ---------------------------------------------------------------------------
// CrossAttention: bf16x3-split mma.sync GEMMs (cp.async + ldmatrix, 1-sync
// pipeline) + fused two-phase flash attention + single-launch prologue.
// R14 base + term-major MMA ordering (volatile kept, no launch_bounds cap).
// ---------------------------------------------------------------------------

#define B_      16
#define N_      2048
#define HEADS_  16
#define DHEAD_  64
#define INNER_  1024
#define CTXL_   333
#define TXT_    77
#define IMG_    256
#define SCALE_  0.125f

#define NX      (33554432LL)
#define NCTX    (16LL * 333 * 1024)

__device__ __nv_bfloat16 g_xh[NX],  g_xl[NX];
__device__ __nv_bfloat16 g_ch[NCTX], g_cl[NCTX];
__device__ __nv_bfloat16 g_Wth[6 * 1048576], g_Wtl[6 * 1048576];
__device__ __nv_bfloat16 g_Qh[NX],  g_Ql[NX];
__device__ __nv_bfloat16 g_Kth[1261568], g_Ktl[1261568];
__device__ __nv_bfloat16 g_Vth[1261568], g_Vtl[1261568];
__device__ __nv_bfloat16 g_Kih[4194304], g_Kil[4194304];
__device__ __nv_bfloat16 g_Vih[4194304], g_Vil[4194304];
__device__ __nv_bfloat16 g_Ah[NX],  g_Al[NX];

// ---------------------------------------------------------------------------
__device__ __forceinline__ uint32_t smem_u32(const void* p) {
    uint32_t a;
    asm("{ .reg .u64 t; cvta.to.shared.u64 t, %1; cvt.u32.u64 %0, t; }"
        : "=r"(a) : "l"(p));
    return a;
}

__device__ __forceinline__ void split2(float x, float y, uint32_t& h, uint32_t& l) {
    __nv_bfloat16 hx = __float2bfloat16(x);
    __nv_bfloat16 hy = __float2bfloat16(y);
    __nv_bfloat16 lx = __float2bfloat16(x - __bfloat162float(hx));
    __nv_bfloat16 ly = __float2bfloat16(y - __bfloat162float(hy));
    h = (uint32_t)__bfloat16_as_ushort(hx) | ((uint32_t)__bfloat16_as_ushort(hy) << 16);
    l = (uint32_t)__bfloat16_as_ushort(lx) | ((uint32_t)__bfloat16_as_ushort(ly) << 16);
}

__device__ __forceinline__ void mma16816(float* c, const uint32_t* a, const uint32_t* b) {
    asm volatile(
        "mma.sync.aligned.m16n8k16.row.col.f32.bf16.bf16.f32 "
        "{%0,%1,%2,%3}, {%4,%5,%6,%7}, {%8,%9}, {%0,%1,%2,%3};"
        : "+f"(c[0]), "+f"(c[1]), "+f"(c[2]), "+f"(c[3])
        : "r"(a[0]), "r"(a[1]), "r"(a[2]), "r"(a[3]), "r"(b[0]), "r"(b[1]));
}

__device__ __forceinline__ void ldsm_x4(uint32_t* r, uint32_t addr) {
    asm volatile("ldmatrix.sync.aligned.m8n8.x4.shared.b16 {%0,%1,%2,%3}, [%4];"
        : "=r"(r[0]), "=r"(r[1]), "=r"(r[2]), "=r"(r[3]) : "r"(addr));
}
__device__ __forceinline__ void ldsm_x4_t(uint32_t* r, uint32_t addr) {
    asm volatile("ldmatrix.sync.aligned.m8n8.x4.trans.shared.b16 {%0,%1,%2,%3}, [%4];"
        : "=r"(r[0]), "=r"(r[1]), "=r"(r[2]), "=r"(r[3]) : "r"(addr));
}

__device__ __forceinline__ void cp16(uint32_t dst, const void* src, int sz) {
    asm volatile("cp.async.cg.shared.global [%0], [%1], 16, %2;"
        :: "r"(dst), "l"(src), "r"(sz));
}
__device__ __forceinline__ void cp_commit() {
    asm volatile("cp.async.commit_group;");
}
__device__ __forceinline__ void cp_wait0() {
    asm volatile("cp.async.wait_group 0;");
}

// ---------------------------------------------------------------------------
// Prologue: ONE launch. [0,8192): x conv; [8192,9524): ctx conv;
// [9524,15668): 6 weight transposes (1024 tiles each).
// ---------------------------------------------------------------------------
__global__ __launch_bounds__(256) void prologue(
    const float* __restrict__ x, const float* __restrict__ ctx,
    const float* __restrict__ W0, const float* __restrict__ W1,
    const float* __restrict__ W2, const float* __restrict__ W3,
    const float* __restrict__ W4, const float* __restrict__ W5)
{
    const int bid = blockIdx.x;
    const int tid = threadIdx.x;

    if (bid < 8192) {
        long long base = (long long)bid * 2048;
        const float2* src = (const float2*)x;
        uint32_t* h = (uint32_t*)g_xh;
        uint32_t* l = (uint32_t*)g_xl;
#pragma unroll
        for (int i = 0; i < 8; i++) {
            long long idx = base + tid + 256 * i;
            float2 v = src[idx];
            uint32_t hh, ll;
            split2(v.x, v.y, hh, ll);
            h[idx] = hh; l[idx] = ll;
        }
    } else if (bid < 9524) {
        long long base = (long long)(bid - 8192) * 2048;
        const float2* src = (const float2*)ctx;
        uint32_t* h = (uint32_t*)g_ch;
        uint32_t* l = (uint32_t*)g_cl;
#pragma unroll
        for (int i = 0; i < 8; i++) {
            long long idx = base + tid + 256 * i;
            float2 v = src[idx];
            uint32_t hh, ll;
            split2(v.x, v.y, hh, ll);
            h[idx] = hh; l[idx] = ll;
        }
    } else {
        __shared__ float ts[32][33];
        int t = bid - 9524;
        int w = t >> 10;
        int tile = t & 1023;
        const float* W = (w == 0) ? W0 : (w == 1) ? W1 : (w == 2) ? W2
                        : (w == 3) ? W3 : (w == 4) ? W4 : W5;
        __nv_bfloat16* Th = g_Wth + (long long)w * 1048576;
        __nv_bfloat16* Tl = g_Wtl + (long long)w * 1048576;
        const int n0 = (tile & 31) * 32, k0 = (tile >> 5) * 32;
        const int tx = tid & 31, ty = tid >> 5;
#pragma unroll
        for (int i = 0; i < 4; i++)
            ts[ty + 8 * i][tx] = W[(long long)(k0 + ty + 8 * i) * 1024 + n0 + tx];
        __syncthreads();
#pragma unroll
        for (int i = 0; i < 4; i++) {
            float v = ts[tx][ty + 8 * i];
            __nv_bfloat16 h = __float2bfloat16(v);
            __nv_bfloat16 l = __float2bfloat16(v - __bfloat162float(h));
            long long o = (long long)(n0 + ty + 8 * i) * 1024 + k0 + tx;
            Th[o] = h; Tl[o] = l;
        }
    }
}

// ---------------------------------------------------------------------------
// Pipelined GEMM: 128x128 tile, 8 warps, K chunk 32, 2-stage cp.async,
// ldmatrix frags, ONE __syncthreads per K-chunk. Term-major MMA order
// (same-acc reuse distance 4) with volatile issue order.
// ---------------------------------------------------------------------------
#define KC    32
#define KPAD  40
#define STG_B (128 * KPAD * 2)
#define GEMM_SMEM (2 * 4 * STG_B)

__global__ __launch_bounds__(256) void gemm_bf16(
    const __nv_bfloat16* __restrict__ Ah, const __nv_bfloat16* __restrict__ Al,
    const __nv_bfloat16* __restrict__ Bh, const __nv_bfloat16* __restrict__ Bl,
    const float* __restrict__ bias, float* __restrict__ Cf,
    __nv_bfloat16* __restrict__ Ch, __nv_bfloat16* __restrict__ Cl,
    int M, int rpb, long long bstride, long long roff, int mode)
{
    extern __shared__ char dynsm[];
    const uint32_t sb = smem_u32(dynsm);

    const int tid  = threadIdx.x;
    const int wid  = tid >> 5;
    const int lane = tid & 31;
    const int gid  = lane >> 2;
    const int tig  = lane & 3;
    const int m0   = blockIdx.y * 128;
    const int n0   = blockIdx.x * 128;
    const int mb   = (wid & 3) * 32;
    const int nb   = (wid >> 2) * 64;

    const int am  = tid >> 1;
    const int akq = (tid & 1) * 16;
    const __nv_bfloat16 *arh, *arl;
    int asz;
    {
        int gm = m0 + am;
        int ok = gm < M;
        int gmc = ok ? gm : 0;
        int bi = gmc / rpb;
        int t2 = gmc - bi * rpb;
        long long off = (long long)bi * bstride + roff + (long long)t2 * 1024 + akq;
        arh = Ah + off; arl = Al + off;
        asz = ok ? 16 : 0;
    }
    const int bn  = tid & 127;
    const int bkq = (tid >> 7) * 16;
    const __nv_bfloat16* brh = Bh + (long long)(n0 + bn) * 1024 + bkq;
    const __nv_bfloat16* brl = Bl + (long long)(n0 + bn) * 1024 + bkq;

    const uint32_t a_off = (uint32_t)(am * (KPAD * 2) + akq * 2);
    const uint32_t b_off = (uint32_t)(bn * (KPAD * 2) + bkq * 2);

    const int a_frag = (mb + (lane & 15)) * KPAD + (lane >> 4) * 8;
    const int b_frag = (nb + (lane >> 4) * 8 + (lane & 7)) * KPAD + ((lane >> 3) & 1) * 8;

    float acc[2][8][4];
#pragma unroll
    for (int mf = 0; mf < 2; mf++)
#pragma unroll
        for (int nf = 0; nf < 8; nf++)
#pragma unroll
            for (int j = 0; j < 4; j++) acc[mf][nf][j] = 0.f;

#define ISSUE(kc, stg) do {                                                  \
        const int k0_ = (kc) * KC;                                           \
        uint32_t bs_ = sb + (stg) * 4 * STG_B;                               \
        cp16(bs_ + a_off,                 arh + k0_,     asz);               \
        cp16(bs_ + a_off + 16,            arh + k0_ + 8, asz);               \
        cp16(bs_ + STG_B + a_off,         arl + k0_,     asz);               \
        cp16(bs_ + STG_B + a_off + 16,    arl + k0_ + 8, asz);               \
        cp16(bs_ + 2 * STG_B + b_off,     brh + k0_,     16);                \
        cp16(bs_ + 2 * STG_B + b_off + 16,brh + k0_ + 8, 16);                \
        cp16(bs_ + 3 * STG_B + b_off,     brl + k0_,     16);                \
        cp16(bs_ + 3 * STG_B + b_off + 16,brl + k0_ + 8, 16);                \
        cp_commit();                                                         \
    } while (0)

    ISSUE(0, 0);

    for (int kc = 0; kc < 32; kc++) {
        const int cur = kc & 1;
        cp_wait0();
        __syncthreads();
        if (kc + 1 < 32) ISSUE(kc + 1, cur ^ 1);

        const uint32_t aH = sb + cur * 4 * STG_B;
        const uint32_t aL = aH + STG_B;
        const uint32_t bH = aH + 2 * STG_B;
        const uint32_t bL = aH + 3 * STG_B;

#pragma unroll
        for (int ks = 0; ks < 2; ks++) {
            uint32_t fah[2][4], fal[2][4];
#pragma unroll
            for (int mf = 0; mf < 2; mf++) {
                uint32_t o = (uint32_t)(2 * (a_frag + mf * 16 * KPAD + ks * 16));
                ldsm_x4(fah[mf], aH + o);
                ldsm_x4(fal[mf], aL + o);
            }
#pragma unroll
            for (int nfp = 0; nfp < 4; nfp++) {
                uint32_t o = (uint32_t)(2 * (b_frag + nfp * 16 * KPAD + ks * 16));
                uint32_t bh4[4], bl4[4];
                ldsm_x4(bh4, bH + o);
                ldsm_x4(bl4, bL + o);
                // term-major: same-acc reuse distance = 4 MMAs
#pragma unroll
                for (int half = 0; half < 2; half++)
#pragma unroll
                    for (int mf = 0; mf < 2; mf++)
                        mma16816(acc[mf][nfp * 2 + half], fah[mf], bh4 + half * 2);
#pragma unroll
                for (int half = 0; half < 2; half++)
#pragma unroll
                    for (int mf = 0; mf < 2; mf++)
                        mma16816(acc[mf][nfp * 2 + half], fal[mf], bh4 + half * 2);
#pragma unroll
                for (int half = 0; half < 2; half++)
#pragma unroll
                    for (int mf = 0; mf < 2; mf++)
                        mma16816(acc[mf][nfp * 2 + half], fah[mf], bl4 + half * 2);
            }
        }
        // no trailing sync: next iteration's wait+sync protects buffer reuse
    }
#undef ISSUE

#pragma unroll
    for (int mf = 0; mf < 2; mf++) {
#pragma unroll
        for (int nf = 0; nf < 8; nf++) {
            int col = n0 + nb + nf * 8 + 2 * tig;
            int r0 = m0 + mb + mf * 16 + gid;
            int r1 = r0 + 8;
            if (mode == 1) {
                float b0 = bias[col], b1 = bias[col + 1];
                if (r0 < M)
                    *(float2*)(Cf + (long long)r0 * 1024 + col) =
                        make_float2(acc[mf][nf][0] + b0, acc[mf][nf][1] + b1);
                if (r1 < M)
                    *(float2*)(Cf + (long long)r1 * 1024 + col) =
                        make_float2(acc[mf][nf][2] + b0, acc[mf][nf][3] + b1);
            } else {
                uint32_t h, l;
                if (r0 < M) {
                    split2(acc[mf][nf][0], acc[mf][nf][1], h, l);
                    *(uint32_t*)(Ch + (long long)r0 * 1024 + col) = h;
                    *(uint32_t*)(Cl + (long long)r0 * 1024 + col) = l;
                }
                if (r1 < M) {
                    split2(acc[mf][nf][2], acc[mf][nf][3], h, l);
                    *(uint32_t*)(Ch + (long long)r1 * 1024 + col) = h;
                    *(uint32_t*)(Cl + (long long)r1 * 1024 + col) = l;
                }
            }
        }
    }
}

// ---------------------------------------------------------------------------
// Fused flash attention: CTA = 128 q rows x 1 head, 8 warps.
// KV chunks of 64 double-buffered via cp.async; linearized txt+img phases.
// Term-major MMA ordering in S and PV loops (distance 2).
// ---------------------------------------------------------------------------
#define APAD  72
#define QS_B  (128 * APAD * 2)
#define KVS_B (64 * APAD * 2)
#define KV_STG (4 * KVS_B)
#define ATT_SMEM (2 * QS_B + 2 * KV_STG)

__global__ __launch_bounds__(256) void attn_fused(
    const __nv_bfloat16* __restrict__ Qh, const __nv_bfloat16* __restrict__ Ql,
    const __nv_bfloat16* __restrict__ K0h, const __nv_bfloat16* __restrict__ K0l,
    const __nv_bfloat16* __restrict__ V0h, const __nv_bfloat16* __restrict__ V0l,
    const __nv_bfloat16* __restrict__ K1h, const __nv_bfloat16* __restrict__ K1l,
    const __nv_bfloat16* __restrict__ V1h, const __nv_bfloat16* __restrict__ V1l,
    __nv_bfloat16* __restrict__ Ah, __nv_bfloat16* __restrict__ Al)
{
    extern __shared__ char dynsm[];
    const uint32_t sb = smem_u32(dynsm);
    const uint32_t sQH = sb, sQL = sb + QS_B;
    const uint32_t kvbase = sb + 2 * QS_B;

    const int tid  = threadIdx.x;
    const int wid  = tid >> 5;
    const int lane = tid & 31;
    const int gid  = lane >> 2;
    const int tig  = lane & 3;
    const int q0   = blockIdx.x * 128;
    const int h    = blockIdx.y;
    const int b    = blockIdx.z;
    const int wr   = wid * 16;

    const __nv_bfloat16* KH[2] = { K0h, K1h };
    const __nv_bfloat16* KL[2] = { K0l, K1l };
    const __nv_bfloat16* VH[2] = { V0h, V1h };
    const __nv_bfloat16* VL[2] = { V0l, V1l };
    const int LP[2] = { TXT_, IMG_ };

    {
        int r = tid >> 1, sc = (tid & 1) * 32;
        long long off = (long long)(b * N_ + q0 + r) * INNER_ + h * DHEAD_ + sc;
        uint32_t d = (uint32_t)(r * (APAD * 2) + sc * 2);
#pragma unroll
        for (int u = 0; u < 4; u++) {
            *(uint4*)(dynsm + d + 16 * u)        = *(const uint4*)(Qh + off + 8 * u);
            *(uint4*)(dynsm + QS_B + d + 16 * u) = *(const uint4*)(Ql + off + 8 * u);
        }
    }

    const int sr = tid >> 2;
    const int sq = (tid & 3) * 16;
    const uint32_t kvd = (uint32_t)(sr * (APAD * 2) + sq * 2);

#define AISSUE(ci) do {                                                       \
        int ph_ = (ci) >= 2;                                                  \
        int c0_ = ph_ ? ((ci) - 2) * 64 : (ci) * 64;                          \
        int L_  = LP[ph_];                                                    \
        int row_ = c0_ + sr;                                                  \
        int ok_  = row_ < L_;                                                 \
        long long off_ = (long long)(b * L_ + (ok_ ? row_ : 0)) * INNER_      \
                         + h * DHEAD_ + sq;                                   \
        int sz_ = ok_ ? 16 : 0;                                               \
        uint32_t bs_ = kvbase + ((ci) & 1) * KV_STG + kvd;                    \
        cp16(bs_,                 KH[ph_] + off_,     sz_);                   \
        cp16(bs_ + 16,            KH[ph_] + off_ + 8, sz_);                   \
        cp16(bs_ + KVS_B,         KL[ph_] + off_,     sz_);                   \
        cp16(bs_ + KVS_B + 16,    KL[ph_] + off_ + 8, sz_);                   \
        cp16(bs_ + 2 * KVS_B,     VH[ph_] + off_,     sz_);                   \
        cp16(bs_ + 2 * KVS_B + 16,VH[ph_] + off_ + 8, sz_);                   \
        cp16(bs_ + 3 * KVS_B,     VL[ph_] + off_,     sz_);                   \
        cp16(bs_ + 3 * KVS_B + 16,VL[ph_] + off_ + 8, sz_);                   \
        cp_commit();                                                          \
    } while (0)

    AISSUE(0);
    __syncthreads();

    uint32_t qfh[4][4], qfl[4][4];
    {
        const int qf = (wr + (lane & 15)) * APAD + (lane >> 4) * 8;
#pragma unroll
        for (int kf = 0; kf < 4; kf++) {
            uint32_t o = (uint32_t)(2 * (qf + kf * 16));
            ldsm_x4(qfh[kf], sQH + o);
            ldsm_x4(qfl[kf], sQL + o);
        }
    }

    const int k_frag = ((lane >> 4) * 8 + (lane & 7)) * APAD + ((lane >> 3) & 1) * 8;
    const int v_frag = (((lane >> 3) & 1) * 8 + (lane & 7)) * APAD + (lane >> 4) * 8;

    float acc[8][4];
#pragma unroll
    for (int nf = 0; nf < 8; nf++)
#pragma unroll
        for (int j = 0; j < 4; j++) acc[nf][j] = 0.f;
    float m0 = -1e30f, m1 = -1e30f, l0 = 0.f, l1 = 0.f;
    float oout[8][4];

    for (int ci = 0; ci < 6; ci++) {
        cp_wait0();
        __syncthreads();
        if (ci + 1 < 6) AISSUE(ci + 1);

        if (ci == 2) {
            float inv0 = 1.f / l0, inv1 = 1.f / l1;
#pragma unroll
            for (int nf = 0; nf < 8; nf++) {
                oout[nf][0] = acc[nf][0] * inv0;
                oout[nf][1] = acc[nf][1] * inv0;
                oout[nf][2] = acc[nf][2] * inv1;
                oout[nf][3] = acc[nf][3] * inv1;
                acc[nf][0] = acc[nf][1] = acc[nf][2] = acc[nf][3] = 0.f;
            }
            m0 = m1 = -1e30f; l0 = l1 = 0.f;
        }

        const int ph_ = ci >= 2;
        const int c0 = ph_ ? (ci - 2) * 64 : ci * 64;
        const int L  = LP[ph_];
        const uint32_t stg = kvbase + (ci & 1) * KV_STG;
        const uint32_t sKH = stg, sKL = stg + KVS_B;
        const uint32_t sVH = stg + 2 * KVS_B, sVL = stg + 3 * KVS_B;

        float s[8][4];
#pragma unroll
        for (int nf = 0; nf < 8; nf++)
#pragma unroll
            for (int j = 0; j < 4; j++) s[nf][j] = 0.f;
#pragma unroll
        for (int kf = 0; kf < 4; kf++) {
#pragma unroll
            for (int nfp = 0; nfp < 4; nfp++) {
                uint32_t o = (uint32_t)(2 * (k_frag + nfp * 16 * APAD + kf * 16));
                uint32_t kh4[4], kl4[4];
                ldsm_x4(kh4, sKH + o);
                ldsm_x4(kl4, sKL + o);
                // term-major: same-s reuse distance = 2
#pragma unroll
                for (int half = 0; half < 2; half++)
                    mma16816(s[nfp * 2 + half], qfh[kf], kh4 + half * 2);
#pragma unroll
                for (int half = 0; half < 2; half++)
                    mma16816(s[nfp * 2 + half], qfl[kf], kh4 + half * 2);
#pragma unroll
                for (int half = 0; half < 2; half++)
                    mma16816(s[nfp * 2 + half], qfh[kf], kl4 + half * 2);
            }
        }

#pragma unroll
        for (int nf = 0; nf < 8; nf++) {
            int col = c0 + nf * 8 + 2 * tig;
            s[nf][0] *= SCALE_; s[nf][1] *= SCALE_;
            s[nf][2] *= SCALE_; s[nf][3] *= SCALE_;
            if (col >= L)     { s[nf][0] = -1e30f; s[nf][2] = -1e30f; }
            if (col + 1 >= L) { s[nf][1] = -1e30f; s[nf][3] = -1e30f; }
        }

        float mx0 = -1e30f, mx1 = -1e30f;
#pragma unroll
        for (int nf = 0; nf < 8; nf++) {
            mx0 = fmaxf(mx0, fmaxf(s[nf][0], s[nf][1]));
            mx1 = fmaxf(mx1, fmaxf(s[nf][2], s[nf][3]));
        }
        mx0 = fmaxf(mx0, __shfl_xor_sync(0xffffffff, mx0, 1));
        mx0 = fmaxf(mx0, __shfl_xor_sync(0xffffffff, mx0, 2));
        mx1 = fmaxf(mx1, __shfl_xor_sync(0xffffffff, mx1, 1));
        mx1 = fmaxf(mx1, __shfl_xor_sync(0xffffffff, mx1, 2));

        float nm0 = fmaxf(m0, mx0), nm1 = fmaxf(m1, mx1);
        float corr0 = __expf(m0 - nm0), corr1 = __expf(m1 - nm1);
        m0 = nm0; m1 = nm1;
#pragma unroll
        for (int nf = 0; nf < 8; nf++) {
            acc[nf][0] *= corr0; acc[nf][1] *= corr0;
            acc[nf][2] *= corr1; acc[nf][3] *= corr1;
        }

        uint32_t ph[8][2], pl[8][2];
        float sum0 = 0.f, sum1 = 0.f;
#pragma unroll
        for (int nf = 0; nf < 8; nf++) {
            float p0 = __expf(s[nf][0] - m0);
            float p1 = __expf(s[nf][1] - m0);
            float p2 = __expf(s[nf][2] - m1);
            float p3 = __expf(s[nf][3] - m1);
            sum0 += p0 + p1; sum1 += p2 + p3;
            split2(p0, p1, ph[nf][0], pl[nf][0]);
            split2(p2, p3, ph[nf][1], pl[nf][1]);
        }
        sum0 += __shfl_xor_sync(0xffffffff, sum0, 1);
        sum0 += __shfl_xor_sync(0xffffffff, sum0, 2);
        sum1 += __shfl_xor_sync(0xffffffff, sum1, 1);
        sum1 += __shfl_xor_sync(0xffffffff, sum1, 2);
        l0 = l0 * corr0 + sum0;
        l1 = l1 * corr1 + sum1;

#pragma unroll
        for (int kf = 0; kf < 4; kf++) {
            uint32_t pah[4] = { ph[2*kf][0], ph[2*kf][1], ph[2*kf+1][0], ph[2*kf+1][1] };
            uint32_t pal[4] = { pl[2*kf][0], pl[2*kf][1], pl[2*kf+1][0], pl[2*kf+1][1] };
#pragma unroll
            for (int dp = 0; dp < 4; dp++) {
                uint32_t o = (uint32_t)(2 * (v_frag + kf * 16 * APAD + dp * 16));
                uint32_t vh4[4], vl4[4];
                ldsm_x4_t(vh4, sVH + o);
                ldsm_x4_t(vl4, sVL + o);
                // term-major: same-acc reuse distance = 2
#pragma unroll
                for (int half = 0; half < 2; half++)
                    mma16816(acc[dp * 2 + half], pah, vh4 + half * 2);
#pragma unroll
                for (int half = 0; half < 2; half++)
                    mma16816(acc[dp * 2 + half], pal, vh4 + half * 2);
#pragma unroll
                for (int half = 0; half < 2; half++)
                    mma16816(acc[dp * 2 + half], pah, vl4 + half * 2);
            }
        }
    }
#undef AISSUE

    const float inv0 = 1.f / l0, inv1 = 1.f / l1;
    const long long r0 = (long long)(b * N_ + q0 + wr + gid);
    const long long r1 = r0 + 8;
#pragma unroll
    for (int nf = 0; nf < 8; nf++) {
        int col = h * DHEAD_ + nf * 8 + 2 * tig;
        uint32_t hh, ll;
        split2(oout[nf][0] + acc[nf][0] * inv0, oout[nf][1] + acc[nf][1] * inv0, hh, ll);
        *(uint32_t*)(Ah + r0 * INNER_ + col) = hh;
        *(uint32_t*)(Al + r0 * INNER_ + col) = ll;
        split2(oout[nf][2] + acc[nf][2] * inv1, oout[nf][3] + acc[nf][3] * inv1, hh, ll);
        *(uint32_t*)(Ah + r1 * INNER_ + col) = hh;
        *(uint32_t*)(Al + r1 * INNER_ + col) = ll;
    }
}

// ---------------------------------------------------------------------------
extern "C" void kernel_launch(void* const* d_in, const int* in_sizes, int n_in,
                              void* d_out, int out_size)
{
    const float* x   = (const float*)d_in[0];
    const float* ctx = (const float*)d_in[1];
    const float* bo  = (const float*)d_in[8];
    float* out = (float*)d_out;

    __nv_bfloat16 *xh, *xl, *ch, *cl, *Wth, *Wtl, *Qh, *Ql;
    __nv_bfloat16 *Kth, *Ktl, *Vth, *Vtl, *Kih, *Kil, *Vih, *Vil, *Ah, *Al;
    cudaGetSymbolAddress((void**)&xh, g_xh);   cudaGetSymbolAddress((void**)&xl, g_xl);
    cudaGetSymbolAddress((void**)&ch, g_ch);   cudaGetSymbolAddress((void**)&cl, g_cl);
    cudaGetSymbolAddress((void**)&Wth, g_Wth); cudaGetSymbolAddress((void**)&Wtl, g_Wtl);
    cudaGetSymbolAddress((void**)&Qh, g_Qh);   cudaGetSymbolAddress((void**)&Ql, g_Ql);
    cudaGetSymbolAddress((void**)&Kth, g_Kth); cudaGetSymbolAddress((void**)&Ktl, g_Ktl);
    cudaGetSymbolAddress((void**)&Vth, g_Vth); cudaGetSymbolAddress((void**)&Vtl, g_Vtl);
    cudaGetSymbolAddress((void**)&Kih, g_Kih); cudaGetSymbolAddress((void**)&Kil, g_Kil);
    cudaGetSymbolAddress((void**)&Vih, g_Vih); cudaGetSymbolAddress((void**)&Vil, g_Vil);
    cudaGetSymbolAddress((void**)&Ah, g_Ah);   cudaGetSymbolAddress((void**)&Al, g_Al);

    cudaFuncSetAttribute(gemm_bf16, cudaFuncAttributeMaxDynamicSharedMemorySize,
                         GEMM_SMEM);
    cudaFuncSetAttribute(attn_fused, cudaFuncAttributeMaxDynamicSharedMemorySize,
                         ATT_SMEM);

    const int M_q   = B_ * N_;
    const int M_txt = B_ * TXT_;
    const int M_img = B_ * IMG_;

    prologue<<<15668, 256>>>(x, ctx,
        (const float*)d_in[2], (const float*)d_in[3], (const float*)d_in[4],
        (const float*)d_in[5], (const float*)d_in[6], (const float*)d_in[7]);

    gemm_bf16<<<dim3(8, 256), 256, GEMM_SMEM>>>(xh, xl, Wth, Wtl, nullptr, nullptr,
        Qh, Ql, M_q, N_, (long long)N_ * 1024, 0, 0);
    gemm_bf16<<<dim3(8, 10), 256, GEMM_SMEM>>>(ch, cl, Wth + 1048576, Wtl + 1048576,
        nullptr, nullptr, Kth, Ktl, M_txt, TXT_, (long long)CTXL_ * 1024, 0, 0);
    gemm_bf16<<<dim3(8, 10), 256, GEMM_SMEM>>>(ch, cl, Wth + 2 * 1048576, Wtl + 2 * 1048576,
        nullptr, nullptr, Vth, Vtl, M_txt, TXT_, (long long)CTXL_ * 1024, 0, 0);
    gemm_bf16<<<dim3(8, 32), 256, GEMM_SMEM>>>(ch, cl, Wth + 3 * 1048576, Wtl + 3 * 1048576,
        nullptr, nullptr, Kih, Kil, M_img, IMG_, (long long)CTXL_ * 1024,
        (long long)TXT_ * 1024, 0);
    gemm_bf16<<<dim3(8, 32), 256, GEMM_SMEM>>>(ch, cl, Wth + 4 * 1048576, Wtl + 4 * 1048576,
        nullptr, nullptr, Vih, Vil, M_img, IMG_, (long long)CTXL_ * 1024,
        (long long)TXT_ * 1024, 0);

    attn_fused<<<dim3(N_ / 128, HEADS_, B_), 256, ATT_SMEM>>>(
        Qh, Ql, Kth, Ktl, Vth, Vtl, Kih, Kil, Vih, Vil, Ah, Al);

    gemm_bf16<<<dim3(8, 256), 256, GEMM_SMEM>>>(Ah, Al, Wth + 5 * 1048576, Wtl + 5 * 1048576,
        bo, out, nullptr, nullptr, M_q, M_q, 0, 0, 1);
}

// round 16
// speedup vs baseline: 1.5125x; 1.5125x over previous
#include <cuda_runtime.h>
#include <cuda_fp16.h>
#include <math.h>
#include <stdint.h>

// ---------------------------------------------------------------------------
// CrossAttention: fp16x2-split mma.sync GEMMs (cp.async + ldmatrix, 1-sync
// pipeline) + fused two-phase flash attention + single-launch prologue.
// Split: D = Ah*Bh + Al*Bh  (fp16 hi/lo on A side, hi only on B side).
// ---------------------------------------------------------------------------

#define B_      16
#define N_      2048
#define HEADS_  16
#define DHEAD_  64
#define INNER_  1024
#define CTXL_   333
#define TXT_    77
#define IMG_    256
#define SCALE_  0.125f

#define NX      (33554432LL)
#define NCTX    (16LL * 333 * 1024)

__device__ __half g_xh[NX],  g_xl[NX];
__device__ __half g_ch[NCTX], g_cl[NCTX];
__device__ __half g_Wth[6 * 1048576];            // weights: hi only
__device__ __half g_Qh[NX],  g_Ql[NX];
__device__ __half g_Kth[1261568];                // K/V: hi only
__device__ __half g_Vth[1261568];
__device__ __half g_Kih[4194304];
__device__ __half g_Vih[4194304];
__device__ __half g_Ah[NX],  g_Al[NX];

// ---------------------------------------------------------------------------
__device__ __forceinline__ uint32_t smem_u32(const void* p) {
    uint32_t a;
    asm("{ .reg .u64 t; cvta.to.shared.u64 t, %1; cvt.u32.u64 %0, t; }"
        : "=r"(a) : "l"(p));
    return a;
}

__device__ __forceinline__ void split2h(float x, float y, uint32_t& h, uint32_t& l) {
    __half hx = __float2half_rn(x);
    __half hy = __float2half_rn(y);
    __half lx = __float2half_rn(x - __half2float(hx));
    __half ly = __float2half_rn(y - __half2float(hy));
    h = (uint32_t)__half_as_ushort(hx) | ((uint32_t)__half_as_ushort(hy) << 16);
    l = (uint32_t)__half_as_ushort(lx) | ((uint32_t)__half_as_ushort(ly) << 16);
}

__device__ __forceinline__ void mma16816(float* c, const uint32_t* a, const uint32_t* b) {
    asm volatile(
        "mma.sync.aligned.m16n8k16.row.col.f32.f16.f16.f32 "
        "{%0,%1,%2,%3}, {%4,%5,%6,%7}, {%8,%9}, {%0,%1,%2,%3};"
        : "+f"(c[0]), "+f"(c[1]), "+f"(c[2]), "+f"(c[3])
        : "r"(a[0]), "r"(a[1]), "r"(a[2]), "r"(a[3]), "r"(b[0]), "r"(b[1]));
}

__device__ __forceinline__ void ldsm_x4(uint32_t* r, uint32_t addr) {
    asm volatile("ldmatrix.sync.aligned.m8n8.x4.shared.b16 {%0,%1,%2,%3}, [%4];"
        : "=r"(r[0]), "=r"(r[1]), "=r"(r[2]), "=r"(r[3]) : "r"(addr));
}
__device__ __forceinline__ void ldsm_x4_t(uint32_t* r, uint32_t addr) {
    asm volatile("ldmatrix.sync.aligned.m8n8.x4.trans.shared.b16 {%0,%1,%2,%3}, [%4];"
        : "=r"(r[0]), "=r"(r[1]), "=r"(r[2]), "=r"(r[3]) : "r"(addr));
}

__device__ __forceinline__ void cp16(uint32_t dst, const void* src, int sz) {
    asm volatile("cp.async.cg.shared.global [%0], [%1], 16, %2;"
        :: "r"(dst), "l"(src), "r"(sz));
}
__device__ __forceinline__ void cp_commit() {
    asm volatile("cp.async.commit_group;");
}
__device__ __forceinline__ void cp_wait0() {
    asm volatile("cp.async.wait_group 0;");
}

// ---------------------------------------------------------------------------
// Prologue: ONE launch. [0,8192): x conv; [8192,9524): ctx conv;
// [9524,15668): 6 weight transposes (hi only).
// ---------------------------------------------------------------------------
__global__ __launch_bounds__(256) void prologue(
    const float* __restrict__ x, const float* __restrict__ ctx,
    const float* __restrict__ W0, const float* __restrict__ W1,
    const float* __restrict__ W2, const float* __restrict__ W3,
    const float* __restrict__ W4, const float* __restrict__ W5)
{
    const int bid = blockIdx.x;
    const int tid = threadIdx.x;

    if (bid < 8192) {
        long long base = (long long)bid * 2048;
        const float2* src = (const float2*)x;
        uint32_t* h = (uint32_t*)g_xh;
        uint32_t* l = (uint32_t*)g_xl;
#pragma unroll
        for (int i = 0; i < 8; i++) {
            long long idx = base + tid + 256 * i;
            float2 v = src[idx];
            uint32_t hh, ll;
            split2h(v.x, v.y, hh, ll);
            h[idx] = hh; l[idx] = ll;
        }
    } else if (bid < 9524) {
        long long base = (long long)(bid - 8192) * 2048;
        const float2* src = (const float2*)ctx;
        uint32_t* h = (uint32_t*)g_ch;
        uint32_t* l = (uint32_t*)g_cl;
#pragma unroll
        for (int i = 0; i < 8; i++) {
            long long idx = base + tid + 256 * i;
            float2 v = src[idx];
            uint32_t hh, ll;
            split2h(v.x, v.y, hh, ll);
            h[idx] = hh; l[idx] = ll;
        }
    } else {
        __shared__ float ts[32][33];
        int t = bid - 9524;
        int w = t >> 10;
        int tile = t & 1023;
        const float* W = (w == 0) ? W0 : (w == 1) ? W1 : (w == 2) ? W2
                        : (w == 3) ? W3 : (w == 4) ? W4 : W5;
        __half* Th = g_Wth + (long long)w * 1048576;
        const int n0 = (tile & 31) * 32, k0 = (tile >> 5) * 32;
        const int tx = tid & 31, ty = tid >> 5;
#pragma unroll
        for (int i = 0; i < 4; i++)
            ts[ty + 8 * i][tx] = W[(long long)(k0 + ty + 8 * i) * 1024 + n0 + tx];
        __syncthreads();
#pragma unroll
        for (int i = 0; i < 4; i++) {
            float v = ts[tx][ty + 8 * i];
            long long o = (long long)(n0 + ty + 8 * i) * 1024 + k0 + tx;
            Th[o] = __float2half_rn(v);
        }
    }
}

// ---------------------------------------------------------------------------
// Pipelined GEMM: 128x128 tile, 8 warps, K chunk 32, 2-stage cp.async,
// ldmatrix frags, ONE __syncthreads per K-chunk. fp16x2 split (A hi/lo,
// B hi only). mode 0: hi+lo out; mode 1: fp32+bias; mode 2: hi only out.
// ---------------------------------------------------------------------------
#define KC    32
#define KPAD  40
#define STG_B (128 * KPAD * 2)
#define GEMM_SMEM (2 * 3 * STG_B)

__global__ __launch_bounds__(256) void gemm_f16(
    const __half* __restrict__ Ah, const __half* __restrict__ Al,
    const __half* __restrict__ Bh,
    const float* __restrict__ bias, float* __restrict__ Cf,
    __half* __restrict__ Ch, __half* __restrict__ Cl,
    int M, int rpb, long long bstride, long long roff, int mode)
{
    extern __shared__ char dynsm[];
    const uint32_t sb = smem_u32(dynsm);

    const int tid  = threadIdx.x;
    const int wid  = tid >> 5;
    const int lane = tid & 31;
    const int gid  = lane >> 2;
    const int tig  = lane & 3;
    const int m0   = blockIdx.y * 128;
    const int n0   = blockIdx.x * 128;
    const int mb   = (wid & 3) * 32;
    const int nb   = (wid >> 2) * 64;

    const int am  = tid >> 1;
    const int akq = (tid & 1) * 16;
    const __half *arh, *arl;
    int asz;
    {
        int gm = m0 + am;
        int ok = gm < M;
        int gmc = ok ? gm : 0;
        int bi = gmc / rpb;
        int t2 = gmc - bi * rpb;
        long long off = (long long)bi * bstride + roff + (long long)t2 * 1024 + akq;
        arh = Ah + off; arl = Al + off;
        asz = ok ? 16 : 0;
    }
    const int bn  = tid & 127;
    const int bkq = (tid >> 7) * 16;
    const __half* brh = Bh + (long long)(n0 + bn) * 1024 + bkq;

    const uint32_t a_off = (uint32_t)(am * (KPAD * 2) + akq * 2);
    const uint32_t b_off = (uint32_t)(bn * (KPAD * 2) + bkq * 2);

    const int a_frag = (mb + (lane & 15)) * KPAD + (lane >> 4) * 8;
    const int b_frag = (nb + (lane >> 4) * 8 + (lane & 7)) * KPAD + ((lane >> 3) & 1) * 8;

    float acc[2][8][4];
#pragma unroll
    for (int mf = 0; mf < 2; mf++)
#pragma unroll
        for (int nf = 0; nf < 8; nf++)
#pragma unroll
            for (int j = 0; j < 4; j++) acc[mf][nf][j] = 0.f;

#define ISSUE(kc, stg) do {                                                  \
        const int k0_ = (kc) * KC;                                           \
        uint32_t bs_ = sb + (stg) * 3 * STG_B;                               \
        cp16(bs_ + a_off,                 arh + k0_,     asz);               \
        cp16(bs_ + a_off + 16,            arh + k0_ + 8, asz);               \
        cp16(bs_ + STG_B + a_off,         arl + k0_,     asz);               \
        cp16(bs_ + STG_B + a_off + 16,    arl + k0_ + 8, asz);               \
        cp16(bs_ + 2 * STG_B + b_off,     brh + k0_,     16);                \
        cp16(bs_ + 2 * STG_B + b_off + 16,brh + k0_ + 8, 16);                \
        cp_commit();                                                         \
    } while (0)

    ISSUE(0, 0);

    for (int kc = 0; kc < 32; kc++) {
        const int cur = kc & 1;
        cp_wait0();
        __syncthreads();
        if (kc + 1 < 32) ISSUE(kc + 1, cur ^ 1);

        const uint32_t aH = sb + cur * 3 * STG_B;
        const uint32_t aL = aH + STG_B;
        const uint32_t bH = aH + 2 * STG_B;

#pragma unroll
        for (int ks = 0; ks < 2; ks++) {
            uint32_t fah[2][4], fal[2][4];
#pragma unroll
            for (int mf = 0; mf < 2; mf++) {
                uint32_t o = (uint32_t)(2 * (a_frag + mf * 16 * KPAD + ks * 16));
                ldsm_x4(fah[mf], aH + o);
                ldsm_x4(fal[mf], aL + o);
            }
#pragma unroll
            for (int nfp = 0; nfp < 4; nfp++) {
                uint32_t o = (uint32_t)(2 * (b_frag + nfp * 16 * KPAD + ks * 16));
                uint32_t bh4[4];
                ldsm_x4(bh4, bH + o);
#pragma unroll
                for (int half = 0; half < 2; half++) {
                    int nf = nfp * 2 + half;
                    uint32_t* bhp = bh4 + half * 2;
#pragma unroll
                    for (int mf = 0; mf < 2; mf++) {
                        mma16816(acc[mf][nf], fah[mf], bhp);
                        mma16816(acc[mf][nf], fal[mf], bhp);
                    }
                }
            }
        }
        // no trailing sync: next iteration's wait+sync protects buffer reuse
    }
#undef ISSUE

#pragma unroll
    for (int mf = 0; mf < 2; mf++) {
#pragma unroll
        for (int nf = 0; nf < 8; nf++) {
            int col = n0 + nb + nf * 8 + 2 * tig;
            int r0 = m0 + mb + mf * 16 + gid;
            int r1 = r0 + 8;
            if (mode == 1) {
                float b0 = bias[col], b1 = bias[col + 1];
                if (r0 < M)
                    *(float2*)(Cf + (long long)r0 * 1024 + col) =
                        make_float2(acc[mf][nf][0] + b0, acc[mf][nf][1] + b1);
                if (r1 < M)
                    *(float2*)(Cf + (long long)r1 * 1024 + col) =
                        make_float2(acc[mf][nf][2] + b0, acc[mf][nf][3] + b1);
            } else if (mode == 0) {
                uint32_t h, l;
                if (r0 < M) {
                    split2h(acc[mf][nf][0], acc[mf][nf][1], h, l);
                    *(uint32_t*)(Ch + (long long)r0 * 1024 + col) = h;
                    *(uint32_t*)(Cl + (long long)r0 * 1024 + col) = l;
                }
                if (r1 < M) {
                    split2h(acc[mf][nf][2], acc[mf][nf][3], h, l);
                    *(uint32_t*)(Ch + (long long)r1 * 1024 + col) = h;
                    *(uint32_t*)(Cl + (long long)r1 * 1024 + col) = l;
                }
            } else {   // mode 2: hi only (K/V projections)
                if (r0 < M) {
                    __half h0 = __float2half_rn(acc[mf][nf][0]);
                    __half h1 = __float2half_rn(acc[mf][nf][1]);
                    *(uint32_t*)(Ch + (long long)r0 * 1024 + col) =
                        (uint32_t)__half_as_ushort(h0) |
                        ((uint32_t)__half_as_ushort(h1) << 16);
                }
                if (r1 < M) {
                    __half h0 = __float2half_rn(acc[mf][nf][2]);
                    __half h1 = __float2half_rn(acc[mf][nf][3]);
                    *(uint32_t*)(Ch + (long long)r1 * 1024 + col) =
                        (uint32_t)__half_as_ushort(h0) |
                        ((uint32_t)__half_as_ushort(h1) << 16);
                }
            }
        }
    }
}

// ---------------------------------------------------------------------------
// Fused flash attention: CTA = 128 q rows x 1 head, 8 warps.
// KV chunks of 64 (hi only!) double-buffered via cp.async; linearized
// txt+img phases. S = Qh*Kh + Ql*Kh;  O += Ph*Vh + Pl*Vh.
// ---------------------------------------------------------------------------
#define APAD  72
#define QS_B  (128 * APAD * 2)
#define KVS_B (64 * APAD * 2)
#define KV_STG (2 * KVS_B)
#define ATT_SMEM (2 * QS_B + 2 * KV_STG)

__global__ __launch_bounds__(256) void attn_fused(
    const __half* __restrict__ Qh, const __half* __restrict__ Ql,
    const __half* __restrict__ K0h, const __half* __restrict__ V0h,
    const __half* __restrict__ K1h, const __half* __restrict__ V1h,
    __half* __restrict__ Ah, __half* __restrict__ Al)
{
    extern __shared__ char dynsm[];
    const uint32_t sb = smem_u32(dynsm);
    const uint32_t sQH = sb, sQL = sb + QS_B;
    const uint32_t kvbase = sb + 2 * QS_B;

    const int tid  = threadIdx.x;
    const int wid  = tid >> 5;
    const int lane = tid & 31;
    const int gid  = lane >> 2;
    const int tig  = lane & 3;
    const int q0   = blockIdx.x * 128;
    const int h    = blockIdx.y;
    const int b    = blockIdx.z;
    const int wr   = wid * 16;

    const __half* KH[2] = { K0h, K1h };
    const __half* VH[2] = { V0h, V1h };
    const int LP[2] = { TXT_, IMG_ };

    {
        int r = tid >> 1, sc = (tid & 1) * 32;
        long long off = (long long)(b * N_ + q0 + r) * INNER_ + h * DHEAD_ + sc;
        uint32_t d = (uint32_t)(r * (APAD * 2) + sc * 2);
#pragma unroll
        for (int u = 0; u < 4; u++) {
            *(uint4*)(dynsm + d + 16 * u)        = *(const uint4*)(Qh + off + 8 * u);
            *(uint4*)(dynsm + QS_B + d + 16 * u) = *(const uint4*)(Ql + off + 8 * u);
        }
    }

    const int sr = tid >> 2;
    const int sq = (tid & 3) * 16;
    const uint32_t kvd = (uint32_t)(sr * (APAD * 2) + sq * 2);

#define AISSUE(ci) do {                                                       \
        int ph_ = (ci) >= 2;                                                  \
        int c0_ = ph_ ? ((ci) - 2) * 64 : (ci) * 64;                          \
        int L_  = LP[ph_];                                                    \
        int row_ = c0_ + sr;                                                  \
        int ok_  = row_ < L_;                                                 \
        long long off_ = (long long)(b * L_ + (ok_ ? row_ : 0)) * INNER_      \
                         + h * DHEAD_ + sq;                                   \
        int sz_ = ok_ ? 16 : 0;                                               \
        uint32_t bs_ = kvbase + ((ci) & 1) * KV_STG + kvd;                    \
        cp16(bs_,              KH[ph_] + off_,     sz_);                      \
        cp16(bs_ + 16,         KH[ph_] + off_ + 8, sz_);                      \
        cp16(bs_ + KVS_B,      VH[ph_] + off_,     sz_);                      \
        cp16(bs_ + KVS_B + 16, VH[ph_] + off_ + 8, sz_);                      \
        cp_commit();                                                          \
    } while (0)

    AISSUE(0);
    __syncthreads();

    uint32_t qfh[4][4], qfl[4][4];
    {
        const int qf = (wr + (lane & 15)) * APAD + (lane >> 4) * 8;
#pragma unroll
        for (int kf = 0; kf < 4; kf++) {
            uint32_t o = (uint32_t)(2 * (qf + kf * 16));
            ldsm_x4(qfh[kf], sQH + o);
            ldsm_x4(qfl[kf], sQL + o);
        }
    }

    const int k_frag = ((lane >> 4) * 8 + (lane & 7)) * APAD + ((lane >> 3) & 1) * 8;
    const int v_frag = (((lane >> 3) & 1) * 8 + (lane & 7)) * APAD + (lane >> 4) * 8;

    float acc[8][4];
#pragma unroll
    for (int nf = 0; nf < 8; nf++)
#pragma unroll
        for (int j = 0; j < 4; j++) acc[nf][j] = 0.f;
    float m0 = -1e30f, m1 = -1e30f, l0 = 0.f, l1 = 0.f;
    float oout[8][4];

    for (int ci = 0; ci < 6; ci++) {
        cp_wait0();
        __syncthreads();
        if (ci + 1 < 6) AISSUE(ci + 1);

        if (ci == 2) {
            float inv0 = 1.f / l0, inv1 = 1.f / l1;
#pragma unroll
            for (int nf = 0; nf < 8; nf++) {
                oout[nf][0] = acc[nf][0] * inv0;
                oout[nf][1] = acc[nf][1] * inv0;
                oout[nf][2] = acc[nf][2] * inv1;
                oout[nf][3] = acc[nf][3] * inv1;
                acc[nf][0] = acc[nf][1] = acc[nf][2] = acc[nf][3] = 0.f;
            }
            m0 = m1 = -1e30f; l0 = l1 = 0.f;
        }

        const int ph_ = ci >= 2;
        const int c0 = ph_ ? (ci - 2) * 64 : ci * 64;
        const int L  = LP[ph_];
        const uint32_t stg = kvbase + (ci & 1) * KV_STG;
        const uint32_t sKH = stg;
        const uint32_t sVH = stg + KVS_B;

        float s[8][4];
#pragma unroll
        for (int nf = 0; nf < 8; nf++)
#pragma unroll
            for (int j = 0; j < 4; j++) s[nf][j] = 0.f;
#pragma unroll
        for (int kf = 0; kf < 4; kf++) {
#pragma unroll
            for (int nfp = 0; nfp < 4; nfp++) {
                uint32_t o = (uint32_t)(2 * (k_frag + nfp * 16 * APAD + kf * 16));
                uint32_t kh4[4];
                ldsm_x4(kh4, sKH + o);
#pragma unroll
                for (int half = 0; half < 2; half++) {
                    int nf = nfp * 2 + half;
                    mma16816(s[nf], qfh[kf], kh4 + half * 2);
                    mma16816(s[nf], qfl[kf], kh4 + half * 2);
                }
            }
        }

#pragma unroll
        for (int nf = 0; nf < 8; nf++) {
            int col = c0 + nf * 8 + 2 * tig;
            s[nf][0] *= SCALE_; s[nf][1] *= SCALE_;
            s[nf][2] *= SCALE_; s[nf][3] *= SCALE_;
            if (col >= L)     { s[nf][0] = -1e30f; s[nf][2] = -1e30f; }
            if (col + 1 >= L) { s[nf][1] = -1e30f; s[nf][3] = -1e30f; }
        }

        float mx0 = -1e30f, mx1 = -1e30f;
#pragma unroll
        for (int nf = 0; nf < 8; nf++) {
            mx0 = fmaxf(mx0, fmaxf(s[nf][0], s[nf][1]));
            mx1 = fmaxf(mx1, fmaxf(s[nf][2], s[nf][3]));
        }
        mx0 = fmaxf(mx0, __shfl_xor_sync(0xffffffff, mx0, 1));
        mx0 = fmaxf(mx0, __shfl_xor_sync(0xffffffff, mx0, 2));
        mx1 = fmaxf(mx1, __shfl_xor_sync(0xffffffff, mx1, 1));
        mx1 = fmaxf(mx1, __shfl_xor_sync(0xffffffff, mx1, 2));

        float nm0 = fmaxf(m0, mx0), nm1 = fmaxf(m1, mx1);
        float corr0 = __expf(m0 - nm0), corr1 = __expf(m1 - nm1);
        m0 = nm0; m1 = nm1;
#pragma unroll
        for (int nf = 0; nf < 8; nf++) {
            acc[nf][0] *= corr0; acc[nf][1] *= corr0;
            acc[nf][2] *= corr1; acc[nf][3] *= corr1;
        }

        uint32_t ph[8][2], pl[8][2];
        float sum0 = 0.f, sum1 = 0.f;
#pragma unroll
        for (int nf = 0; nf < 8; nf++) {
            float p0 = __expf(s[nf][0] - m0);
            float p1 = __expf(s[nf][1] - m0);
            float p2 = __expf(s[nf][2] - m1);
            float p3 = __expf(s[nf][3] - m1);
            sum0 += p0 + p1; sum1 += p2 + p3;
            split2h(p0, p1, ph[nf][0], pl[nf][0]);
            split2h(p2, p3, ph[nf][1], pl[nf][1]);
        }
        sum0 += __shfl_xor_sync(0xffffffff, sum0, 1);
        sum0 += __shfl_xor_sync(0xffffffff, sum0, 2);
        sum1 += __shfl_xor_sync(0xffffffff, sum1, 1);
        sum1 += __shfl_xor_sync(0xffffffff, sum1, 2);
        l0 = l0 * corr0 + sum0;
        l1 = l1 * corr1 + sum1;

#pragma unroll
        for (int kf = 0; kf < 4; kf++) {
            uint32_t pah[4] = { ph[2*kf][0], ph[2*kf][1], ph[2*kf+1][0], ph[2*kf+1][1] };
            uint32_t pal[4] = { pl[2*kf][0], pl[2*kf][1], pl[2*kf+1][0], pl[2*kf+1][1] };
#pragma unroll
            for (int dp = 0; dp < 4; dp++) {
                uint32_t o = (uint32_t)(2 * (v_frag + kf * 16 * APAD + dp * 16));
                uint32_t vh4[4];
                ldsm_x4_t(vh4, sVH + o);
#pragma unroll
                for (int half = 0; half < 2; half++) {
                    int nfo = dp * 2 + half;
                    mma16816(acc[nfo], pah, vh4 + half * 2);
                    mma16816(acc[nfo], pal, vh4 + half * 2);
                }
            }
        }
    }
#undef AISSUE

    const float inv0 = 1.f / l0, inv1 = 1.f / l1;
    const long long r0 = (long long)(b * N_ + q0 + wr + gid);
    const long long r1 = r0 + 8;
#pragma unroll
    for (int nf = 0; nf < 8; nf++) {
        int col = h * DHEAD_ + nf * 8 + 2 * tig;
        uint32_t hh, ll;
        split2h(oout[nf][0] + acc[nf][0] * inv0, oout[nf][1] + acc[nf][1] * inv0, hh, ll);
        *(uint32_t*)(Ah + r0 * INNER_ + col) = hh;
        *(uint32_t*)(Al + r0 * INNER_ + col) = ll;
        split2h(oout[nf][2] + acc[nf][2] * inv1, oout[nf][3] + acc[nf][3] * inv1, hh, ll);
        *(uint32_t*)(Ah + r1 * INNER_ + col) = hh;
        *(uint32_t*)(Al + r1 * INNER_ + col) = ll;
    }
}

// ---------------------------------------------------------------------------
extern "C" void kernel_launch(void* const* d_in, const int* in_sizes, int n_in,
                              void* d_out, int out_size)
{
    const float* x   = (const float*)d_in[0];
    const float* ctx = (const float*)d_in[1];
    const float* bo  = (const float*)d_in[8];
    float* out = (float*)d_out;

    __half *xh, *xl, *ch, *cl, *Wth, *Qh, *Ql;
    __half *Kth, *Vth, *Kih, *Vih, *Ah, *Al;
    cudaGetSymbolAddress((void**)&xh, g_xh);   cudaGetSymbolAddress((void**)&xl, g_xl);
    cudaGetSymbolAddress((void**)&ch, g_ch);   cudaGetSymbolAddress((void**)&cl, g_cl);
    cudaGetSymbolAddress((void**)&Wth, g_Wth);
    cudaGetSymbolAddress((void**)&Qh, g_Qh);   cudaGetSymbolAddress((void**)&Ql, g_Ql);
    cudaGetSymbolAddress((void**)&Kth, g_Kth);
    cudaGetSymbolAddress((void**)&Vth, g_Vth);
    cudaGetSymbolAddress((void**)&Kih, g_Kih);
    cudaGetSymbolAddress((void**)&Vih, g_Vih);
    cudaGetSymbolAddress((void**)&Ah, g_Ah);   cudaGetSymbolAddress((void**)&Al, g_Al);

    cudaFuncSetAttribute(gemm_f16, cudaFuncAttributeMaxDynamicSharedMemorySize,
                         GEMM_SMEM);
    cudaFuncSetAttribute(attn_fused, cudaFuncAttributeMaxDynamicSharedMemorySize,
                         ATT_SMEM);

    const int M_q   = B_ * N_;
    const int M_txt = B_ * TXT_;
    const int M_img = B_ * IMG_;

    prologue<<<15668, 256>>>(x, ctx,
        (const float*)d_in[2], (const float*)d_in[3], (const float*)d_in[4],
        (const float*)d_in[5], (const float*)d_in[6], (const float*)d_in[7]);

    // Q projection: hi+lo output (A-side of attention)
    gemm_f16<<<dim3(8, 256), 256, GEMM_SMEM>>>(xh, xl, Wth, nullptr, nullptr,
        Qh, Ql, M_q, N_, (long long)N_ * 1024, 0, 0);
    // K/V projections: hi-only output (B-side of attention)
    gemm_f16<<<dim3(8, 10), 256, GEMM_SMEM>>>(ch, cl, Wth + 1048576,
        nullptr, nullptr, Kth, nullptr, M_txt, TXT_, (long long)CTXL_ * 1024, 0, 2);
    gemm_f16<<<dim3(8, 10), 256, GEMM_SMEM>>>(ch, cl, Wth + 2 * 1048576,
        nullptr, nullptr, Vth, nullptr, M_txt, TXT_, (long long)CTXL_ * 1024, 0, 2);
    gemm_f16<<<dim3(8, 32), 256, GEMM_SMEM>>>(ch, cl, Wth + 3 * 1048576,
        nullptr, nullptr, Kih, nullptr, M_img, IMG_, (long long)CTXL_ * 1024,
        (long long)TXT_ * 1024, 2);
    gemm_f16<<<dim3(8, 32), 256, GEMM_SMEM>>>(ch, cl, Wth + 4 * 1048576,
        nullptr, nullptr, Vih, nullptr, M_img, IMG_, (long long)CTXL_ * 1024,
        (long long)TXT_ * 1024, 2);

    attn_fused<<<dim3(N_ / 128, HEADS_, B_), 256, ATT_SMEM>>>(
        Qh, Ql, Kth, Vth, Kih, Vih, Ah, Al);

    // Output projection: fp32 + bias
    gemm_f16<<<dim3(8, 256), 256, GEMM_SMEM>>>(Ah, Al, Wth + 5 * 1048576,
        bo, out, nullptr, nullptr, M_q, M_q, 0, 0, 1);
}